// round 1
// baseline (speedup 1.0000x reference)
#include <cuda_runtime.h>
#include <math.h>

#define HID 1024
#define NHEADS 16
#define HEADDIM 64
#define BATCH 2
#define SEQ 2048
#define MROWS (BATCH * SEQ)   // 4096

// ---------------- scratch (static device arrays; no allocation) ----------------
__device__ float g_q [(size_t)MROWS * HID];        // 16.8 MB
__device__ float g_kv[(size_t)MROWS * 2 * HID];    // 33.6 MB
__device__ float g_y [(size_t)MROWS * HID];        // 16.8 MB

// ---------------- SGEMM: C[M,N] = A[M,K] * B[K,N], row-major, fp32 --------------
// BM=BN=128, BK=8, 256 threads, 8x8 microtile. Dims must divide tiles (they do).
#define GBM 128
#define GBN 128
#define GBK 8
#define GTM 8
#define GTN 8

__global__ __launch_bounds__(256, 2)
void sgemm_kernel(const float* __restrict__ A, const float* __restrict__ B,
                  float* __restrict__ C, int M, int N, int K) {
    __shared__ float As[GBK][GBM];   // transposed A tile
    __shared__ float Bs[GBK][GBN];

    const int bx = blockIdx.x;   // N tile
    const int by = blockIdx.y;   // M tile
    const int tid = threadIdx.x;
    const int tx = tid & 15;     // 16 cols of threads
    const int ty = tid >> 4;     // 16 rows of threads

    // A tile load: 128 rows x 8 cols, one float4 per thread
    const int aRow = tid >> 1;             // 0..127
    const int aCol = (tid & 1) << 2;       // 0 or 4
    // B tile load: 8 rows x 128 cols, one float4 per thread
    const int bRow = tid >> 5;             // 0..7
    const int bCol = (tid & 31) << 2;      // 0..124

    const float* Ab = A + (size_t)(by * GBM) * K;
    const float* Bb = B + (size_t)(bx * GBN);

    float acc[GTM][GTN];
    #pragma unroll
    for (int i = 0; i < GTM; i++)
        #pragma unroll
        for (int j = 0; j < GTN; j++) acc[i][j] = 0.f;

    for (int k0 = 0; k0 < K; k0 += GBK) {
        float4 a4 = *(const float4*)(Ab + (size_t)aRow * K + k0 + aCol);
        As[aCol + 0][aRow] = a4.x;
        As[aCol + 1][aRow] = a4.y;
        As[aCol + 2][aRow] = a4.z;
        As[aCol + 3][aRow] = a4.w;
        float4 b4 = *(const float4*)(Bb + (size_t)(k0 + bRow) * N + bCol);
        *(float4*)&Bs[bRow][bCol] = b4;
        __syncthreads();

        #pragma unroll
        for (int kk = 0; kk < GBK; kk++) {
            float ar[GTM], br[GTN];
            #pragma unroll
            for (int i = 0; i < GTM; i += 4)
                *(float4*)&ar[i] = *(float4*)&As[kk][ty * GTM + i];
            #pragma unroll
            for (int j = 0; j < GTN; j += 4)
                *(float4*)&br[j] = *(float4*)&Bs[kk][tx * GTN + j];
            #pragma unroll
            for (int i = 0; i < GTM; i++)
                #pragma unroll
                for (int j = 0; j < GTN; j++)
                    acc[i][j] = fmaf(ar[i], br[j], acc[i][j]);
        }
        __syncthreads();
    }

    float* Cb = C + (size_t)(by * GBM + ty * GTM) * N + bx * GBN + tx * GTN;
    #pragma unroll
    for (int i = 0; i < GTM; i++)
        #pragma unroll
        for (int j = 0; j < GTN; j += 4)
            *(float4*)(Cb + (size_t)i * N + j) =
                make_float4(acc[i][j], acc[i][j+1], acc[i][j+2], acc[i][j+3]);
}

// ---------------- Flash attention ----------------
// One CTA: one (b,h) pair x one 64-query tile. Loop over T in 64-key chunks.
// 256 threads = 16x16 grid, each thread owns a 4(row)x4(col) microtile.
// smem: sqT[d][r] (q transposed, pre-scaled), skT[d][t], Vs[t][d], Ps[t][r].
__global__ __launch_bounds__(256, 3)
void flash_attn_kernel(const float* __restrict__ gq, const float* __restrict__ gkv,
                       float* __restrict__ gy) {
    extern __shared__ float sm[];
    float* sqT = sm;            // 64*64
    float* skT = sm + 4096;     // 64*64
    float* Vs  = sm + 8192;     // 64*64
    float* Ps  = sm + 12288;    // 64*64

    const int bh = blockIdx.y;          // 0..31
    const int b  = bh >> 4;
    const int h  = bh & 15;
    const int q0 = blockIdx.x << 6;     // query tile start
    const int tid = threadIdx.x;
    const int tx = tid & 15;
    const int ty = tid >> 4;
    const float scale = 0.125f;         // 1/sqrt(64)

    // load q tile, transposed + scaled
    #pragma unroll
    for (int it = 0; it < 4; it++) {
        int f   = tid + (it << 8);
        int row = f >> 4;
        int d4  = (f & 15) << 2;
        float4 v = *(const float4*)(gq + (size_t)(b * SEQ + q0 + row) * HID + h * HEADDIM + d4);
        sqT[(d4 + 0) * 64 + row] = v.x * scale;
        sqT[(d4 + 1) * 64 + row] = v.y * scale;
        sqT[(d4 + 2) * 64 + row] = v.z * scale;
        sqT[(d4 + 3) * 64 + row] = v.w * scale;
    }

    float m[4], l[4], o[4][4];
    #pragma unroll
    for (int i = 0; i < 4; i++) {
        m[i] = -INFINITY; l[i] = 0.f;
        #pragma unroll
        for (int j = 0; j < 4; j++) o[i][j] = 0.f;
    }

    const float* kbase = gkv + (size_t)(b * SEQ) * (2 * HID) + h * HEADDIM;
    const float* vbase = kbase + HID;

    for (int t0 = 0; t0 < SEQ; t0 += 64) {
        __syncthreads();  // previous chunk's PV reads of skT/Vs done
        #pragma unroll
        for (int it = 0; it < 4; it++) {
            int f   = tid + (it << 8);
            int row = f >> 4;
            int d4  = (f & 15) << 2;
            float4 k4 = *(const float4*)(kbase + (size_t)(t0 + row) * (2 * HID) + d4);
            skT[(d4 + 0) * 64 + row] = k4.x;
            skT[(d4 + 1) * 64 + row] = k4.y;
            skT[(d4 + 2) * 64 + row] = k4.z;
            skT[(d4 + 3) * 64 + row] = k4.w;
            float4 v4 = *(const float4*)(vbase + (size_t)(t0 + row) * (2 * HID) + d4);
            *(float4*)(Vs + row * 64 + d4) = v4;
        }
        __syncthreads();

        // S = (q*scale) . k^T   — 4x4 per thread
        float s[4][4];
        #pragma unroll
        for (int i = 0; i < 4; i++)
            #pragma unroll
            for (int j = 0; j < 4; j++) s[i][j] = 0.f;
        #pragma unroll 8
        for (int d = 0; d < 64; d++) {
            float4 a  = *(float4*)(sqT + d * 64 + (ty << 2));
            float4 bb = *(float4*)(skT + d * 64 + (tx << 2));
            float ar[4] = {a.x, a.y, a.z, a.w};
            float br[4] = {bb.x, bb.y, bb.z, bb.w};
            #pragma unroll
            for (int i = 0; i < 4; i++)
                #pragma unroll
                for (int j = 0; j < 4; j++)
                    s[i][j] = fmaf(ar[i], br[j], s[i][j]);
        }

        // online softmax per query row (16 tx-threads share a row: half-warp shfl)
        #pragma unroll
        for (int i = 0; i < 4; i++) {
            float mx = fmaxf(fmaxf(s[i][0], s[i][1]), fmaxf(s[i][2], s[i][3]));
            #pragma unroll
            for (int off = 1; off < 16; off <<= 1)
                mx = fmaxf(mx, __shfl_xor_sync(0xffffffffu, mx, off));
            float mnew = fmaxf(m[i], mx);
            float corr = __expf(m[i] - mnew);
            float p[4], rs = 0.f;
            #pragma unroll
            for (int j = 0; j < 4; j++) { p[j] = __expf(s[i][j] - mnew); rs += p[j]; }
            #pragma unroll
            for (int off = 1; off < 16; off <<= 1)
                rs += __shfl_xor_sync(0xffffffffu, rs, off);
            l[i] = l[i] * corr + rs;
            m[i] = mnew;
            #pragma unroll
            for (int j = 0; j < 4; j++) o[i][j] *= corr;
            // store P transposed: Ps[t][r]
            #pragma unroll
            for (int j = 0; j < 4; j++)
                Ps[((tx << 2) + j) * 64 + (ty << 2) + i] = p[j];
        }
        __syncthreads();

        // O += P . V   (thread owns rows ty*4.., hd cols tx*4..)
        #pragma unroll 8
        for (int t = 0; t < 64; t++) {
            float4 a  = *(float4*)(Ps + t * 64 + (ty << 2));
            float4 bb = *(float4*)(Vs + t * 64 + (tx << 2));
            float ar[4] = {a.x, a.y, a.z, a.w};
            float br[4] = {bb.x, bb.y, bb.z, bb.w};
            #pragma unroll
            for (int i = 0; i < 4; i++)
                #pragma unroll
                for (int j = 0; j < 4; j++)
                    o[i][j] = fmaf(ar[i], br[j], o[i][j]);
        }
    }

    // epilogue: normalize and store y
    #pragma unroll
    for (int i = 0; i < 4; i++) {
        float inv = 1.f / l[i];
        float4 w = make_float4(o[i][0] * inv, o[i][1] * inv, o[i][2] * inv, o[i][3] * inv);
        *(float4*)(gy + (size_t)(b * SEQ + q0 + (ty << 2) + i) * HID + h * HEADDIM + (tx << 2)) = w;
    }
}

// ---------------- launch ----------------
extern "C" void kernel_launch(void* const* d_in, const int* in_sizes, int n_in,
                              void* d_out, int out_size) {
    const float* query     = (const float*)d_in[0];
    const float* key_value = (const float*)d_in[1];
    const float* Wq        = (const float*)d_in[2];
    const float* Wkv       = (const float*)d_in[3];
    const float* Wc        = (const float*)d_in[4];
    float* out = (float*)d_out;

    float *q, *kv, *y;
    cudaGetSymbolAddress((void**)&q,  g_q);
    cudaGetSymbolAddress((void**)&kv, g_kv);
    cudaGetSymbolAddress((void**)&y,  g_y);

    // 64 KB dynamic smem for flash kernel (idempotent; not an allocation)
    cudaFuncSetAttribute(flash_attn_kernel,
                         cudaFuncAttributeMaxDynamicSharedMemorySize, 64 * 1024);

    // 1) q = query @ Wq        [4096,1024] = [4096,1024]x[1024,1024]
    sgemm_kernel<<<dim3(HID / GBN, MROWS / GBM), 256>>>(query, Wq, q, MROWS, HID, HID);
    // 2) kv = key_value @ Wkv  [4096,2048] = [4096,1024]x[1024,2048]
    sgemm_kernel<<<dim3(2 * HID / GBN, MROWS / GBM), 256>>>(key_value, Wkv, kv, MROWS, 2 * HID, HID);
    // 3) flash attention -> y
    flash_attn_kernel<<<dim3(SEQ / 64, BATCH * NHEADS), 256, 64 * 1024>>>(q, kv, y);
    // 4) out = y @ Wc          [4096,1024] = [4096,1024]x[1024,1024]
    sgemm_kernel<<<dim3(HID / GBN, MROWS / GBM), 256>>>(y, Wc, out, MROWS, HID, HID);
}

// round 3
// speedup vs baseline: 2.9738x; 2.9738x over previous
#include <cuda_runtime.h>
#include <cuda_bf16.h>
#include <math.h>
#include <stdint.h>

#define HID 1024
#define NHEADS 16
#define HEADDIM 64
#define BATCH 2
#define SEQ 2048
#define MROWS (BATCH * SEQ)   // 4096

typedef __nv_bfloat16 bf16;

// ---------------- scratch (static device arrays; no allocation) ----------------
__device__ bf16 g_qin_h [(size_t)MROWS * HID];
__device__ bf16 g_qin_l [(size_t)MROWS * HID];
__device__ bf16 g_kvin_h[(size_t)MROWS * HID];
__device__ bf16 g_kvin_l[(size_t)MROWS * HID];
__device__ bf16 g_qh    [(size_t)MROWS * HID];
__device__ bf16 g_ql    [(size_t)MROWS * HID];
__device__ bf16 g_kvh   [(size_t)MROWS * 2 * HID];
__device__ bf16 g_kvl   [(size_t)MROWS * 2 * HID];
__device__ bf16 g_yh    [(size_t)MROWS * HID];
__device__ bf16 g_yl    [(size_t)MROWS * HID];
__device__ bf16 g_wqT_h [(size_t)HID * HID];
__device__ bf16 g_wqT_l [(size_t)HID * HID];
__device__ bf16 g_wkvT_h[(size_t)2 * HID * HID];
__device__ bf16 g_wkvT_l[(size_t)2 * HID * HID];
__device__ bf16 g_wcT_h [(size_t)HID * HID];
__device__ bf16 g_wcT_l [(size_t)HID * HID];

// ---------------- PTX helpers (compute_103-safe: no tcgen05) ----------------
__device__ __forceinline__ uint32_t smem_u32(const void* p) {
    uint32_t a;
    asm("{ .reg .u64 t; cvta.to.shared.u64 t, %1; cvt.u32.u64 %0, t; }" : "=r"(a) : "l"(p));
    return a;
}
__device__ __forceinline__ void cp16(uint32_t s, const void* g) {
    asm volatile("cp.async.cg.shared.global [%0], [%1], 16;" :: "r"(s), "l"(g));
}
#define CP_COMMIT() asm volatile("cp.async.commit_group;" ::: "memory")
#define CP_WAIT1()  asm volatile("cp.async.wait_group 1;" ::: "memory")

__device__ __forceinline__ void ldsm4(uint32_t* r, uint32_t a) {
    asm volatile("ldmatrix.sync.aligned.m8n8.x4.shared.b16 {%0,%1,%2,%3}, [%4];"
                 : "=r"(r[0]), "=r"(r[1]), "=r"(r[2]), "=r"(r[3]) : "r"(a));
}
__device__ __forceinline__ void ldsm4t(uint32_t* r, uint32_t a) {
    asm volatile("ldmatrix.sync.aligned.m8n8.x4.trans.shared.b16 {%0,%1,%2,%3}, [%4];"
                 : "=r"(r[0]), "=r"(r[1]), "=r"(r[2]), "=r"(r[3]) : "r"(a));
}
__device__ __forceinline__ void mma16816(float* d, const uint32_t* a, const uint32_t* b) {
    asm volatile(
        "mma.sync.aligned.m16n8k16.row.col.f32.bf16.bf16.f32 "
        "{%0,%1,%2,%3}, {%4,%5,%6,%7}, {%8,%9}, {%0,%1,%2,%3};"
        : "+f"(d[0]), "+f"(d[1]), "+f"(d[2]), "+f"(d[3])
        : "r"(a[0]), "r"(a[1]), "r"(a[2]), "r"(a[3]), "r"(b[0]), "r"(b[1]));
}

__device__ __forceinline__ uint32_t pack2(float a, float b) {
    __nv_bfloat162 t = __floats2bfloat162_rn(a, b);
    return *(uint32_t*)&t;
}
__device__ __forceinline__ uint32_t pack2_res(float a, float b, uint32_t hpk) {
    __nv_bfloat162 hh = *(__nv_bfloat162*)&hpk;
    return pack2(a - __bfloat162float(hh.x), b - __bfloat162float(hh.y));
}
__device__ __forceinline__ void split_store(bf16* H, bf16* L, size_t idx, float a, float b) {
    uint32_t h = pack2(a, b);
    uint32_t l = pack2_res(a, b, h);
    *(uint32_t*)(H + idx) = h;
    *(uint32_t*)(L + idx) = l;
}

// ================= split-bf16 mma.sync GEMM =================
// C[M,N] = (Ah+Al)[M,K] . (Bh+Bl)^T, B stored [N,K] row-major (pre-transposed).
// CTA tile 128x128, BK=32, 8 warps (4m x 2n), warp tile 32x64.
#define GP    80      // smem pitch bytes per 32-bf16 row (conflict-free LDSM)
#define GMAT  10240   // 128 rows * 80B
#define GSTG  40960   // 4 matrices per stage
#define GSMEM (2 * GSTG)

__global__ __launch_bounds__(256, 1)
void gemm_mma(const bf16* __restrict__ Ah, const bf16* __restrict__ Al,
              const bf16* __restrict__ Bh, const bf16* __restrict__ Bl,
              float* __restrict__ Cf, bf16* __restrict__ Ch, bf16* __restrict__ Cl,
              int M, int N, int K, int mode, float scale) {
    extern __shared__ __align__(128) char smem[];
    const uint32_t sb = smem_u32(smem);
    const int tid = threadIdx.x, lane = tid & 31, wid = tid >> 5;
    const int m0 = blockIdx.y << 7, n0 = blockIdx.x << 7;
    const int wm = (wid >> 1) << 5, wn = (wid & 1) << 6;

    // lane offsets for ldmatrix addressing
    const int arow  = (lane & 7) + ((lane >> 3) & 1) * 8;  // A-operand rows
    const int akoff = ((lane >> 4) << 3);                  // A-operand k offset
    const int brow  = (lane & 7) + ((lane >> 4) << 3);     // B-operand rows (non-trans)
    const int bkoff = ((lane >> 3) & 1) * 8;               // B-operand k offset

    float acc[2][8][4];
    #pragma unroll
    for (int i = 0; i < 2; i++)
        #pragma unroll
        for (int j = 0; j < 8; j++)
            #pragma unroll
            for (int r = 0; r < 4; r++) acc[i][j][r] = 0.f;

    const int NCH = K >> 5;

    // preload chunk 0
    {
        uint32_t d = sb;
        #pragma unroll
        for (int i = 0; i < 2; i++) {
            int idx = tid + (i << 8);
            int row = idx >> 2, c = idx & 3;
            uint32_t off = row * GP + c * 16;
            cp16(d + off,            Ah + (size_t)(m0 + row) * K + c * 8);
            cp16(d + GMAT + off,     Al + (size_t)(m0 + row) * K + c * 8);
            cp16(d + 2 * GMAT + off, Bh + (size_t)(n0 + row) * K + c * 8);
            cp16(d + 3 * GMAT + off, Bl + (size_t)(n0 + row) * K + c * 8);
        }
    }
    CP_COMMIT();

    for (int ch = 0; ch < NCH; ch++) {
        if (ch + 1 < NCH) {
            uint32_t d = sb + ((ch + 1) & 1) * GSTG;
            int k0 = (ch + 1) << 5;
            #pragma unroll
            for (int i = 0; i < 2; i++) {
                int idx = tid + (i << 8);
                int row = idx >> 2, c = idx & 3;
                uint32_t off = row * GP + c * 16;
                cp16(d + off,            Ah + (size_t)(m0 + row) * K + k0 + c * 8);
                cp16(d + GMAT + off,     Al + (size_t)(m0 + row) * K + k0 + c * 8);
                cp16(d + 2 * GMAT + off, Bh + (size_t)(n0 + row) * K + k0 + c * 8);
                cp16(d + 3 * GMAT + off, Bl + (size_t)(n0 + row) * K + k0 + c * 8);
            }
        }
        CP_COMMIT();
        CP_WAIT1();
        __syncthreads();

        const uint32_t base = sb + (ch & 1) * GSTG;
        #pragma unroll
        for (int kk = 0; kk < 2; kk++) {
            uint32_t ah[2][4], al[2][4];
            #pragma unroll
            for (int sm = 0; sm < 2; sm++) {
                uint32_t aoff = (wm + sm * 16 + arow) * GP + (kk * 16 + akoff) * 2;
                ldsm4(ah[sm], base + aoff);
                ldsm4(al[sm], base + GMAT + aoff);
            }
            uint32_t bh4[4][4], bl4[4][4];
            #pragma unroll
            for (int q = 0; q < 4; q++) {
                uint32_t boff = (wn + q * 16 + brow) * GP + (kk * 16 + bkoff) * 2;
                ldsm4(bh4[q], base + 2 * GMAT + boff);
                ldsm4(bl4[q], base + 3 * GMAT + boff);
            }
            #pragma unroll
            for (int sm = 0; sm < 2; sm++)
                #pragma unroll
                for (int nt = 0; nt < 8; nt++) {
                    const uint32_t* BH = &bh4[nt >> 1][(nt & 1) << 1];
                    const uint32_t* BL = &bl4[nt >> 1][(nt & 1) << 1];
                    mma16816(acc[sm][nt], ah[sm], BH);
                    mma16816(acc[sm][nt], ah[sm], BL);
                    mma16816(acc[sm][nt], al[sm], BH);
                }
        }
        __syncthreads();
    }

    // epilogue
    const int r0 = wm + (lane >> 2);
    const int c0 = wn + ((lane & 3) << 1);
    #pragma unroll
    for (int sm = 0; sm < 2; sm++)
        #pragma unroll
        for (int nt = 0; nt < 8; nt++) {
            int row = m0 + r0 + sm * 16;
            int col = n0 + c0 + nt * 8;
            if (mode == 0) {
                *(float2*)(Cf + (size_t)row * N + col) =
                    make_float2(acc[sm][nt][0], acc[sm][nt][1]);
                *(float2*)(Cf + (size_t)(row + 8) * N + col) =
                    make_float2(acc[sm][nt][2], acc[sm][nt][3]);
            } else {
                split_store(Ch, Cl, (size_t)row * N + col,
                            acc[sm][nt][0] * scale, acc[sm][nt][1] * scale);
                split_store(Ch, Cl, (size_t)(row + 8) * N + col,
                            acc[sm][nt][2] * scale, acc[sm][nt][3] * scale);
            }
        }
}

// ================= flash attention on mma.sync =================
// CTA: 128 queries x one (b,h). 8 warps, each warp 16 q rows. K/V chunks of 64.
// smem: Qh/Ql 128x64 (pitch 144B), 2 stages of {Kh,Kl,Vh,Vl} 64x64 (pitch 144B).
#define AP     144                  // pitch bytes per 64-bf16 row
#define AQMAT  (128 * AP)           // 18432
#define AKMAT  (64 * AP)            // 9216
#define ASTG   (4 * AKMAT)          // 36864
#define ASMEM  (2 * AQMAT + 2 * ASTG)

__global__ __launch_bounds__(256, 1)
void attn_mma(const bf16* __restrict__ qh, const bf16* __restrict__ ql,
              const bf16* __restrict__ kvh, const bf16* __restrict__ kvl,
              bf16* __restrict__ yh, bf16* __restrict__ yl) {
    extern __shared__ __align__(128) char smem[];
    const uint32_t sb = smem_u32(smem);
    const int tid = threadIdx.x, lane = tid & 31, wid = tid >> 5;
    const int bh = blockIdx.y;
    const int b = bh >> 4, h = bh & 15;
    const int q0 = blockIdx.x << 7;

    const int arow  = (lane & 7) + ((lane >> 3) & 1) * 8;
    const int akoff = ((lane >> 4) << 3);
    const int brow  = (lane & 7) + ((lane >> 4) << 3);
    const int bkoff = ((lane >> 3) & 1) * 8;

    const uint32_t sQh = sb, sQl = sb + AQMAT;
    const uint32_t sKV = sb + 2 * AQMAT;

    // --- load Q tile (128 x 64) hi/lo ---
    {
        #pragma unroll
        for (int i = 0; i < 4; i++) {
            int idx = tid + (i << 8);
            int row = idx >> 3, c = idx & 7;
            uint32_t off = row * AP + c * 16;
            const size_t g = (size_t)(b * SEQ + q0 + row) * HID + h * HEADDIM + c * 8;
            cp16(sQh + off, qh + g);
            cp16(sQl + off, ql + g);
        }
    }
    CP_COMMIT();

    // --- preload KV chunk 0 ---
    const size_t kvrow0 = (size_t)(b * SEQ);
    {
        #pragma unroll
        for (int i = 0; i < 2; i++) {
            int idx = tid + (i << 8);
            int row = idx >> 3, c = idx & 7;
            uint32_t off = row * AP + c * 16;
            size_t gk = (kvrow0 + row) * (2 * HID) + h * HEADDIM + c * 8;
            size_t gv = gk + HID;
            cp16(sKV + off,             kvh + gk);
            cp16(sKV + AKMAT + off,     kvl + gk);
            cp16(sKV + 2 * AKMAT + off, kvh + gv);
            cp16(sKV + 3 * AKMAT + off, kvl + gv);
        }
    }
    CP_COMMIT();
    CP_WAIT1();       // Q resident (chunk0 may be in flight)
    __syncthreads();

    // --- Q fragments in registers ---
    uint32_t qfh[4][4], qfl[4][4];
    #pragma unroll
    for (int kk = 0; kk < 4; kk++) {
        uint32_t off = (wid * 16 + arow) * AP + (kk * 16 + akoff) * 2;
        ldsm4(qfh[kk], sQh + off);
        ldsm4(qfl[kk], sQl + off);
    }

    float o[8][4];
    #pragma unroll
    for (int i = 0; i < 8; i++)
        #pragma unroll
        for (int r = 0; r < 4; r++) o[i][r] = 0.f;
    float m0_ = -INFINITY, m1_ = -INFINITY, l0_ = 0.f, l1_ = 0.f;

    const int NCH = SEQ / 64;
    for (int ch = 0; ch < NCH; ch++) {
        if (ch + 1 < NCH) {
            uint32_t d = sKV + ((ch + 1) & 1) * ASTG;
            int t0 = (ch + 1) << 6;
            #pragma unroll
            for (int i = 0; i < 2; i++) {
                int idx = tid + (i << 8);
                int row = idx >> 3, c = idx & 7;
                uint32_t off = row * AP + c * 16;
                size_t gk = (kvrow0 + t0 + row) * (2 * HID) + h * HEADDIM + c * 8;
                size_t gv = gk + HID;
                cp16(d + off,             kvh + gk);
                cp16(d + AKMAT + off,     kvl + gk);
                cp16(d + 2 * AKMAT + off, kvh + gv);
                cp16(d + 3 * AKMAT + off, kvl + gv);
            }
        }
        CP_COMMIT();
        CP_WAIT1();
        __syncthreads();

        const uint32_t sK = sKV + (ch & 1) * ASTG;
        const uint32_t sV = sK + 2 * AKMAT;

        // ---- S = Q . K^T ----
        float s[8][4];
        #pragma unroll
        for (int i = 0; i < 8; i++)
            #pragma unroll
            for (int r = 0; r < 4; r++) s[i][r] = 0.f;
        #pragma unroll
        for (int kk = 0; kk < 4; kk++) {
            uint32_t kb[4][4], kl4[4][4];
            #pragma unroll
            for (int q = 0; q < 4; q++) {
                uint32_t off = (q * 16 + brow) * AP + (kk * 16 + bkoff) * 2;
                ldsm4(kb[q],  sK + off);
                ldsm4(kl4[q], sK + AKMAT + off);
            }
            #pragma unroll
            for (int nt = 0; nt < 8; nt++) {
                const uint32_t* BH = &kb[nt >> 1][(nt & 1) << 1];
                const uint32_t* BL = &kl4[nt >> 1][(nt & 1) << 1];
                mma16816(s[nt], qfh[kk], BH);
                mma16816(s[nt], qfh[kk], BL);
                mma16816(s[nt], qfl[kk], BH);
            }
        }

        // ---- online softmax ----
        float mx0 = -INFINITY, mx1 = -INFINITY;
        #pragma unroll
        for (int nt = 0; nt < 8; nt++) {
            mx0 = fmaxf(mx0, fmaxf(s[nt][0], s[nt][1]));
            mx1 = fmaxf(mx1, fmaxf(s[nt][2], s[nt][3]));
        }
        mx0 = fmaxf(mx0, __shfl_xor_sync(0xffffffffu, mx0, 1));
        mx0 = fmaxf(mx0, __shfl_xor_sync(0xffffffffu, mx0, 2));
        mx1 = fmaxf(mx1, __shfl_xor_sync(0xffffffffu, mx1, 1));
        mx1 = fmaxf(mx1, __shfl_xor_sync(0xffffffffu, mx1, 2));
        float mn0 = fmaxf(m0_, mx0), mn1 = fmaxf(m1_, mx1);
        float corr0 = __expf(m0_ - mn0), corr1 = __expf(m1_ - mn1);
        m0_ = mn0; m1_ = mn1;
        float rs0 = 0.f, rs1 = 0.f;
        #pragma unroll
        for (int nt = 0; nt < 8; nt++) {
            s[nt][0] = __expf(s[nt][0] - mn0); rs0 += s[nt][0];
            s[nt][1] = __expf(s[nt][1] - mn0); rs0 += s[nt][1];
            s[nt][2] = __expf(s[nt][2] - mn1); rs1 += s[nt][2];
            s[nt][3] = __expf(s[nt][3] - mn1); rs1 += s[nt][3];
        }
        rs0 += __shfl_xor_sync(0xffffffffu, rs0, 1);
        rs0 += __shfl_xor_sync(0xffffffffu, rs0, 2);
        rs1 += __shfl_xor_sync(0xffffffffu, rs1, 1);
        rs1 += __shfl_xor_sync(0xffffffffu, rs1, 2);
        l0_ = l0_ * corr0 + rs0;
        l1_ = l1_ * corr1 + rs1;
        #pragma unroll
        for (int dt = 0; dt < 8; dt++) {
            o[dt][0] *= corr0; o[dt][1] *= corr0;
            o[dt][2] *= corr1; o[dt][3] *= corr1;
        }

        // ---- P fragments (A-operand layout) ----
        uint32_t ph[4][4], pl[4][4];
        #pragma unroll
        for (int j = 0; j < 4; j++) {
            ph[j][0] = pack2(s[2 * j][0], s[2 * j][1]);
            ph[j][1] = pack2(s[2 * j][2], s[2 * j][3]);
            ph[j][2] = pack2(s[2 * j + 1][0], s[2 * j + 1][1]);
            ph[j][3] = pack2(s[2 * j + 1][2], s[2 * j + 1][3]);
            pl[j][0] = pack2_res(s[2 * j][0], s[2 * j][1], ph[j][0]);
            pl[j][1] = pack2_res(s[2 * j][2], s[2 * j][3], ph[j][1]);
            pl[j][2] = pack2_res(s[2 * j + 1][0], s[2 * j + 1][1], ph[j][2]);
            pl[j][3] = pack2_res(s[2 * j + 1][2], s[2 * j + 1][3], ph[j][3]);
        }

        // ---- O += P . V ----
        #pragma unroll
        for (int j = 0; j < 4; j++) {
            uint32_t vb[4][4], vl4[4][4];
            #pragma unroll
            for (int dq = 0; dq < 4; dq++) {
                uint32_t off = (j * 16 + arow) * AP + (dq * 16 + akoff) * 2;
                ldsm4t(vb[dq],  sV + off);
                ldsm4t(vl4[dq], sV + AKMAT + off);
            }
            #pragma unroll
            for (int dt = 0; dt < 8; dt++) {
                const uint32_t* VH = &vb[dt >> 1][(dt & 1) << 1];
                const uint32_t* VL = &vl4[dt >> 1][(dt & 1) << 1];
                mma16816(o[dt], ph[j], VH);
                mma16816(o[dt], ph[j], VL);
                mma16816(o[dt], pl[j], VH);
            }
        }
        __syncthreads();
    }

    // ---- epilogue: normalize, split-store y ----
    const float inv0 = 1.f / l0_, inv1 = 1.f / l1_;
    const int gr = b * SEQ + q0 + wid * 16 + (lane >> 2);
    const int col = h * HEADDIM + ((lane & 3) << 1);
    #pragma unroll
    for (int dt = 0; dt < 8; dt++) {
        split_store(yh, yl, (size_t)gr * HID + col + dt * 8,
                    o[dt][0] * inv0, o[dt][1] * inv0);
        split_store(yh, yl, (size_t)(gr + 8) * HID + col + dt * 8,
                    o[dt][2] * inv1, o[dt][3] * inv1);
    }
}

// ---------------- converters ----------------
__global__ void convert_act(const float* __restrict__ in, bf16* __restrict__ h,
                            bf16* __restrict__ l, int n) {
    int i = (blockIdx.x * blockDim.x + threadIdx.x) << 2;
    if (i >= n) return;
    float4 v = *(const float4*)(in + i);
    uint32_t h0 = pack2(v.x, v.y), h1 = pack2(v.z, v.w);
    uint32_t l0 = pack2_res(v.x, v.y, h0), l1 = pack2_res(v.z, v.w, h1);
    *(uint32_t*)(h + i) = h0; *(uint32_t*)(h + i + 2) = h1;
    *(uint32_t*)(l + i) = l0; *(uint32_t*)(l + i + 2) = l1;
}

// W[K,N] fp32 -> Th/Tl[N,K] bf16 (transpose + split)
__global__ void trconv(const float* __restrict__ W, bf16* __restrict__ Th,
                       bf16* __restrict__ Tl, int K, int N) {
    __shared__ float t[32][33];
    const int n0 = blockIdx.x << 5, k0 = blockIdx.y << 5;
    const int tx = threadIdx.x, ty = threadIdx.y;
    #pragma unroll
    for (int j = 0; j < 32; j += 8)
        t[ty + j][tx] = W[(size_t)(k0 + ty + j) * N + n0 + tx];
    __syncthreads();
    #pragma unroll
    for (int j = 0; j < 32; j += 8) {
        float v = t[tx][ty + j];
        bf16 hv = __float2bfloat16(v);
        bf16 lv = __float2bfloat16(v - __bfloat162float(hv));
        size_t off = (size_t)(n0 + ty + j) * K + k0 + tx;
        Th[off] = hv;
        Tl[off] = lv;
    }
}

// ---------------- launch ----------------
extern "C" void kernel_launch(void* const* d_in, const int* in_sizes, int n_in,
                              void* d_out, int out_size) {
    const float* query     = (const float*)d_in[0];
    const float* key_value = (const float*)d_in[1];
    const float* Wq        = (const float*)d_in[2];
    const float* Wkv       = (const float*)d_in[3];
    const float* Wc        = (const float*)d_in[4];
    float* out = (float*)d_out;

    bf16 *qin_h, *qin_l, *kvin_h, *kvin_l, *qqh, *qql, *kvh, *kvl, *yh, *yl;
    bf16 *wqT_h, *wqT_l, *wkvT_h, *wkvT_l, *wcT_h, *wcT_l;
    cudaGetSymbolAddress((void**)&qin_h,  g_qin_h);
    cudaGetSymbolAddress((void**)&qin_l,  g_qin_l);
    cudaGetSymbolAddress((void**)&kvin_h, g_kvin_h);
    cudaGetSymbolAddress((void**)&kvin_l, g_kvin_l);
    cudaGetSymbolAddress((void**)&qqh,    g_qh);
    cudaGetSymbolAddress((void**)&qql,    g_ql);
    cudaGetSymbolAddress((void**)&kvh,    g_kvh);
    cudaGetSymbolAddress((void**)&kvl,    g_kvl);
    cudaGetSymbolAddress((void**)&yh,     g_yh);
    cudaGetSymbolAddress((void**)&yl,     g_yl);
    cudaGetSymbolAddress((void**)&wqT_h,  g_wqT_h);
    cudaGetSymbolAddress((void**)&wqT_l,  g_wqT_l);
    cudaGetSymbolAddress((void**)&wkvT_h, g_wkvT_h);
    cudaGetSymbolAddress((void**)&wkvT_l, g_wkvT_l);
    cudaGetSymbolAddress((void**)&wcT_h,  g_wcT_h);
    cudaGetSymbolAddress((void**)&wcT_l,  g_wcT_l);

    cudaFuncSetAttribute(gemm_mma, cudaFuncAttributeMaxDynamicSharedMemorySize, GSMEM);
    cudaFuncSetAttribute(attn_mma, cudaFuncAttributeMaxDynamicSharedMemorySize, ASMEM);

    // 1) split/convert inputs + weights
    {
        int n = MROWS * HID;
        convert_act<<<n / 4 / 256, 256>>>(query, qin_h, qin_l, n);
        convert_act<<<n / 4 / 256, 256>>>(key_value, kvin_h, kvin_l, n);
    }
    trconv<<<dim3(HID / 32, HID / 32),     dim3(32, 8)>>>(Wq,  wqT_h,  wqT_l,  HID, HID);
    trconv<<<dim3(2 * HID / 32, HID / 32), dim3(32, 8)>>>(Wkv, wkvT_h, wkvT_l, HID, 2 * HID);
    trconv<<<dim3(HID / 32, HID / 32),     dim3(32, 8)>>>(Wc,  wcT_h,  wcT_l,  HID, HID);

    // 2) q = (query @ Wq) * 0.125, split bf16 out
    gemm_mma<<<dim3(HID / 128, MROWS / 128), 256, GSMEM>>>(
        qin_h, qin_l, wqT_h, wqT_l, nullptr, qqh, qql, MROWS, HID, HID, 1, 0.125f);
    // 3) kv = key_value @ Wkv, split bf16 out
    gemm_mma<<<dim3(2 * HID / 128, MROWS / 128), 256, GSMEM>>>(
        kvin_h, kvin_l, wkvT_h, wkvT_l, nullptr, kvh, kvl, MROWS, 2 * HID, HID, 1, 1.0f);
    // 4) flash attention -> y (split bf16)
    attn_mma<<<dim3(SEQ / 128, BATCH * NHEADS), 256, ASMEM>>>(qqh, qql, kvh, kvl, yh, yl);
    // 5) out = y @ Wc, fp32 out
    gemm_mma<<<dim3(HID / 128, MROWS / 128), 256, GSMEM>>>(
        yh, yl, wcT_h, wcT_l, out, nullptr, nullptr, MROWS, HID, HID, 0, 0.f);
}

// round 9
// speedup vs baseline: 3.0404x; 1.0224x over previous
#include <cuda_runtime.h>
#include <cuda_bf16.h>
#include <math.h>
#include <stdint.h>

#define HID 1024
#define NHEADS 16
#define HEADDIM 64
#define BATCH 2
#define SEQ 2048
#define MROWS (BATCH * SEQ)   // 4096

#define QSCALE (0.125f * 1.4426950408889634f)   // 1/sqrt(64) * log2(e), folded into q

typedef __nv_bfloat16 bf16;

// ---------------- scratch ----------------
__device__ bf16 g_qin_h [(size_t)MROWS * HID];
__device__ bf16 g_qin_l [(size_t)MROWS * HID];
__device__ bf16 g_kvin_h[(size_t)MROWS * HID];
__device__ bf16 g_kvin_l[(size_t)MROWS * HID];
__device__ bf16 g_qh    [(size_t)MROWS * HID];
__device__ bf16 g_ql    [(size_t)MROWS * HID];
__device__ bf16 g_kvh   [(size_t)MROWS * 2 * HID];
__device__ bf16 g_kvl   [(size_t)MROWS * 2 * HID];
__device__ bf16 g_yh    [(size_t)MROWS * HID];
__device__ bf16 g_yl    [(size_t)MROWS * HID];
__device__ bf16 g_wqT_h [(size_t)HID * HID];
__device__ bf16 g_wqT_l [(size_t)HID * HID];
__device__ bf16 g_wkvT_h[(size_t)2 * HID * HID];
__device__ bf16 g_wkvT_l[(size_t)2 * HID * HID];
__device__ bf16 g_wcT_h [(size_t)HID * HID];
__device__ bf16 g_wcT_l [(size_t)HID * HID];

// ---------------- PTX helpers ----------------
__device__ __forceinline__ uint32_t smem_u32(const void* p) {
    uint32_t a;
    asm("{ .reg .u64 t; cvta.to.shared.u64 t, %1; cvt.u32.u64 %0, t; }" : "=r"(a) : "l"(p));
    return a;
}
__device__ __forceinline__ void cp16(uint32_t s, const void* g) {
    asm volatile("cp.async.cg.shared.global [%0], [%1], 16;" :: "r"(s), "l"(g));
}
#define CP_COMMIT() asm volatile("cp.async.commit_group;" ::: "memory")
#define CP_WAIT1()  asm volatile("cp.async.wait_group 1;" ::: "memory")

__device__ __forceinline__ void ldsm4(uint32_t* r, uint32_t a) {
    asm volatile("ldmatrix.sync.aligned.m8n8.x4.shared.b16 {%0,%1,%2,%3}, [%4];"
                 : "=r"(r[0]), "=r"(r[1]), "=r"(r[2]), "=r"(r[3]) : "r"(a));
}
__device__ __forceinline__ void ldsm4t(uint32_t* r, uint32_t a) {
    asm volatile("ldmatrix.sync.aligned.m8n8.x4.trans.shared.b16 {%0,%1,%2,%3}, [%4];"
                 : "=r"(r[0]), "=r"(r[1]), "=r"(r[2]), "=r"(r[3]) : "r"(a));
}
__device__ __forceinline__ void mma16816(float* d, const uint32_t* a, const uint32_t* b) {
    asm volatile(
        "mma.sync.aligned.m16n8k16.row.col.f32.bf16.bf16.f32 "
        "{%0,%1,%2,%3}, {%4,%5,%6,%7}, {%8,%9}, {%0,%1,%2,%3};"
        : "+f"(d[0]), "+f"(d[1]), "+f"(d[2]), "+f"(d[3])
        : "r"(a[0]), "r"(a[1]), "r"(a[2]), "r"(a[3]), "r"(b[0]), "r"(b[1]));
}

__device__ __forceinline__ uint32_t pack2(float a, float b) {
    __nv_bfloat162 t = __floats2bfloat162_rn(a, b);
    return *(uint32_t*)&t;
}
__device__ __forceinline__ uint32_t pack2_res(float a, float b, uint32_t hpk) {
    __nv_bfloat162 hh = *(__nv_bfloat162*)&hpk;
    return pack2(a - __bfloat162float(hh.x), b - __bfloat162float(hh.y));
}
__device__ __forceinline__ void split_store(bf16* H, bf16* L, size_t idx, float a, float b) {
    uint32_t h = pack2(a, b);
    uint32_t l = pack2_res(a, b, h);
    *(uint32_t*)(H + idx) = h;
    *(uint32_t*)(L + idx) = l;
}

// ================= split-bf16 mma.sync GEMM core =================
// C[M,N] = (Ah+Al)[M,K] . (Bh+Bl)^T, B stored [N,K] row-major.
// CTA tile 128x128, BK=32, 8 warps (4m x 2n), warp tile 32x64.
#define GP    80
#define GMAT  10240
#define GSTG  40960
#define GSMEM (2 * GSTG)

template<int MODE>   // 0: fp32 out, 1: split-bf16 out (scaled)
__device__ __forceinline__ void gemm_core(
    uint32_t sb,
    const bf16* __restrict__ Ah, const bf16* __restrict__ Al,
    const bf16* __restrict__ Bh, const bf16* __restrict__ Bl,
    float* __restrict__ Cf, bf16* __restrict__ Ch, bf16* __restrict__ Cl,
    int N, int K, int m0, int n0, float scale) {
    const int tid = threadIdx.x, lane = tid & 31, wid = tid >> 5;
    const int wm = (wid >> 1) << 5, wn = (wid & 1) << 6;

    const int arow  = (lane & 7) + ((lane >> 3) & 1) * 8;
    const int akoff = ((lane >> 4) << 3);
    const int brow  = (lane & 7) + ((lane >> 4) << 3);
    const int bkoff = ((lane >> 3) & 1) * 8;

    float acc[2][8][4];
    #pragma unroll
    for (int i = 0; i < 2; i++)
        #pragma unroll
        for (int j = 0; j < 8; j++)
            #pragma unroll
            for (int r = 0; r < 4; r++) acc[i][j][r] = 0.f;

    const int NCH = K >> 5;

    {
        uint32_t d = sb;
        #pragma unroll
        for (int i = 0; i < 2; i++) {
            int idx = tid + (i << 8);
            int row = idx >> 2, c = idx & 3;
            uint32_t off = row * GP + c * 16;
            cp16(d + off,            Ah + (size_t)(m0 + row) * K + c * 8);
            cp16(d + GMAT + off,     Al + (size_t)(m0 + row) * K + c * 8);
            cp16(d + 2 * GMAT + off, Bh + (size_t)(n0 + row) * K + c * 8);
            cp16(d + 3 * GMAT + off, Bl + (size_t)(n0 + row) * K + c * 8);
        }
    }
    CP_COMMIT();

    for (int ch = 0; ch < NCH; ch++) {
        if (ch + 1 < NCH) {
            uint32_t d = sb + ((ch + 1) & 1) * GSTG;
            int k0 = (ch + 1) << 5;
            #pragma unroll
            for (int i = 0; i < 2; i++) {
                int idx = tid + (i << 8);
                int row = idx >> 2, c = idx & 3;
                uint32_t off = row * GP + c * 16;
                cp16(d + off,            Ah + (size_t)(m0 + row) * K + k0 + c * 8);
                cp16(d + GMAT + off,     Al + (size_t)(m0 + row) * K + k0 + c * 8);
                cp16(d + 2 * GMAT + off, Bh + (size_t)(n0 + row) * K + k0 + c * 8);
                cp16(d + 3 * GMAT + off, Bl + (size_t)(n0 + row) * K + k0 + c * 8);
            }
        }
        CP_COMMIT();
        CP_WAIT1();
        __syncthreads();

        const uint32_t base = sb + (ch & 1) * GSTG;
        #pragma unroll
        for (int kk = 0; kk < 2; kk++) {
            uint32_t ah[2][4], al[2][4];
            #pragma unroll
            for (int sm = 0; sm < 2; sm++) {
                uint32_t aoff = (wm + sm * 16 + arow) * GP + (kk * 16 + akoff) * 2;
                ldsm4(ah[sm], base + aoff);
                ldsm4(al[sm], base + GMAT + aoff);
            }
            uint32_t bh4[4][4], bl4[4][4];
            #pragma unroll
            for (int q = 0; q < 4; q++) {
                uint32_t boff = (wn + q * 16 + brow) * GP + (kk * 16 + bkoff) * 2;
                ldsm4(bh4[q], base + 2 * GMAT + boff);
                ldsm4(bl4[q], base + 3 * GMAT + boff);
            }
            #pragma unroll
            for (int sm = 0; sm < 2; sm++)
                #pragma unroll
                for (int nt = 0; nt < 8; nt++) {
                    const uint32_t* BH = &bh4[nt >> 1][(nt & 1) << 1];
                    const uint32_t* BL = &bl4[nt >> 1][(nt & 1) << 1];
                    mma16816(acc[sm][nt], ah[sm], BH);
                    mma16816(acc[sm][nt], ah[sm], BL);
                    mma16816(acc[sm][nt], al[sm], BH);
                }
        }
        __syncthreads();
    }

    const int r0 = wm + (lane >> 2);
    const int c0 = wn + ((lane & 3) << 1);
    #pragma unroll
    for (int sm = 0; sm < 2; sm++)
        #pragma unroll
        for (int nt = 0; nt < 8; nt++) {
            int row = m0 + r0 + sm * 16;
            int col = n0 + c0 + nt * 8;
            if (MODE == 0) {
                *(float2*)(Cf + (size_t)row * N + col) =
                    make_float2(acc[sm][nt][0], acc[sm][nt][1]);
                *(float2*)(Cf + (size_t)(row + 8) * N + col) =
                    make_float2(acc[sm][nt][2], acc[sm][nt][3]);
            } else {
                split_store(Ch, Cl, (size_t)row * N + col,
                            acc[sm][nt][0] * scale, acc[sm][nt][1] * scale);
                split_store(Ch, Cl, (size_t)(row + 8) * N + col,
                            acc[sm][nt][2] * scale, acc[sm][nt][3] * scale);
            }
        }
}

// merged q-proj + kv-proj (independent GEMMs, one launch: kills wave tails)
__global__ __launch_bounds__(256, 1)
void proj_gemm(const bf16* __restrict__ qinh, const bf16* __restrict__ qinl,
               const bf16* __restrict__ kvinh, const bf16* __restrict__ kvinl,
               const bf16* __restrict__ wqh, const bf16* __restrict__ wql,
               const bf16* __restrict__ wkvh, const bf16* __restrict__ wkvl,
               bf16* __restrict__ qh, bf16* __restrict__ ql,
               bf16* __restrict__ kvh, bf16* __restrict__ kvl) {
    extern __shared__ __align__(128) char smem[];
    const uint32_t sb = smem_u32(smem);
    const int bx = blockIdx.x, m0 = blockIdx.y << 7;
    if (bx < HID / 128) {
        gemm_core<1>(sb, qinh, qinl, wqh, wql, nullptr, qh, ql,
                     HID, HID, m0, bx << 7, QSCALE);
    } else {
        gemm_core<1>(sb, kvinh, kvinl, wkvh, wkvl, nullptr, kvh, kvl,
                     2 * HID, HID, m0, (bx - HID / 128) << 7, 1.0f);
    }
}

__global__ __launch_bounds__(256, 1)
void out_gemm(const bf16* __restrict__ yh, const bf16* __restrict__ yl,
              const bf16* __restrict__ wch, const bf16* __restrict__ wcl,
              float* __restrict__ out) {
    extern __shared__ __align__(128) char smem[];
    const uint32_t sb = smem_u32(smem);
    gemm_core<0>(sb, yh, yl, wch, wcl, out, nullptr, nullptr,
                 HID, HID, blockIdx.y << 7, blockIdx.x << 7, 0.f);
}

// ================= flash attention on mma.sync =================
// CTA: 128 queries x one (b,h). 8 warps. KV iterations of 128 rows = 2 sub-chunks.
// Single max/correction/rescale per 128 rows; PV(A) interleaves with softmax(B).
#define AP     144
#define AQMAT  (128 * AP)            // 18432 (one Q matrix)
#define AM2    (128 * AP)            // 18432 (one KV matrix, 128 rows)
#define ASTG   (4 * AM2)             // 73728 per stage {Kh,Kl,Vh,Vl}
#define ASMEM  (2 * AQMAT + 2 * ASTG)  // 184320

__global__ __launch_bounds__(256, 1)
void attn_mma(const bf16* __restrict__ qh, const bf16* __restrict__ ql,
              const bf16* __restrict__ kvh, const bf16* __restrict__ kvl,
              bf16* __restrict__ yh, bf16* __restrict__ yl) {
    extern __shared__ __align__(128) char smem[];
    const uint32_t sb = smem_u32(smem);
    const int tid = threadIdx.x, lane = tid & 31, wid = tid >> 5;
    const int bh = blockIdx.y;
    const int b = bh >> 4, h = bh & 15;
    const int q0 = blockIdx.x << 7;

    const int arow  = (lane & 7) + ((lane >> 3) & 1) * 8;
    const int akoff = ((lane >> 4) << 3);
    const int brow  = (lane & 7) + ((lane >> 4) << 3);
    const int bkoff = ((lane >> 3) & 1) * 8;

    const uint32_t sQh = sb, sQl = sb + AQMAT;
    const uint32_t sKV = sb + 2 * AQMAT;

    // --- load Q tile (128 x 64) hi/lo ---
    #pragma unroll
    for (int i = 0; i < 4; i++) {
        int idx = tid + (i << 8);
        int row = idx >> 3, c = idx & 7;
        uint32_t off = row * AP + c * 16;
        const size_t g = (size_t)(b * SEQ + q0 + row) * HID + h * HEADDIM + c * 8;
        cp16(sQh + off, qh + g);
        cp16(sQl + off, ql + g);
    }
    CP_COMMIT();

    // --- preload KV iter 0 (128 rows) ---
    const size_t kvrow0 = (size_t)(b * SEQ);
    #pragma unroll
    for (int i = 0; i < 4; i++) {
        int idx = tid + (i << 8);
        int row = idx >> 3, c = idx & 7;
        uint32_t off = row * AP + c * 16;
        size_t gk = (kvrow0 + row) * (2 * HID) + h * HEADDIM + c * 8;
        size_t gv = gk + HID;
        cp16(sKV + off,           kvh + gk);
        cp16(sKV + AM2 + off,     kvl + gk);
        cp16(sKV + 2 * AM2 + off, kvh + gv);
        cp16(sKV + 3 * AM2 + off, kvl + gv);
    }
    CP_COMMIT();
    CP_WAIT1();        // Q resident
    __syncthreads();

    uint32_t qfh[4][4], qfl[4][4];
    #pragma unroll
    for (int kk = 0; kk < 4; kk++) {
        uint32_t off = (wid * 16 + arow) * AP + (kk * 16 + akoff) * 2;
        ldsm4(qfh[kk], sQh + off);
        ldsm4(qfl[kk], sQl + off);
    }

    float o[8][4];
    #pragma unroll
    for (int i = 0; i < 8; i++)
        #pragma unroll
        for (int r = 0; r < 4; r++) o[i][r] = 0.f;
    float m0_ = -INFINITY, m1_ = -INFINITY, l0_ = 0.f, l1_ = 0.f;

    const int NIT = SEQ / 128;
    for (int ch = 0; ch < NIT; ch++) {
        if (ch + 1 < NIT) {
            uint32_t d = sKV + ((ch + 1) & 1) * ASTG;
            int t0 = (ch + 1) << 7;
            #pragma unroll
            for (int i = 0; i < 4; i++) {
                int idx = tid + (i << 8);
                int row = idx >> 3, c = idx & 7;
                uint32_t off = row * AP + c * 16;
                size_t gk = (kvrow0 + t0 + row) * (2 * HID) + h * HEADDIM + c * 8;
                size_t gv = gk + HID;
                cp16(d + off,           kvh + gk);
                cp16(d + AM2 + off,     kvl + gk);
                cp16(d + 2 * AM2 + off, kvh + gv);
                cp16(d + 3 * AM2 + off, kvl + gv);
            }
        }
        CP_COMMIT();
        CP_WAIT1();
        __syncthreads();

        const uint32_t sK = sKV + (ch & 1) * ASTG;
        const uint32_t sV = sK + 2 * AM2;

        // ---- S_A (keys 0-63), S_B (keys 64-127) ----
        float sA[8][4], sB[8][4];
        #pragma unroll
        for (int i = 0; i < 8; i++)
            #pragma unroll
            for (int r = 0; r < 4; r++) { sA[i][r] = 0.f; sB[i][r] = 0.f; }

        #pragma unroll
        for (int kk = 0; kk < 4; kk++) {
            uint32_t kb[4][4], kl4[4][4];
            #pragma unroll
            for (int q = 0; q < 4; q++) {
                uint32_t off = (q * 16 + brow) * AP + (kk * 16 + bkoff) * 2;
                ldsm4(kb[q],  sK + off);
                ldsm4(kl4[q], sK + AM2 + off);
            }
            #pragma unroll
            for (int nt = 0; nt < 8; nt++) {
                const uint32_t* BH = &kb[nt >> 1][(nt & 1) << 1];
                const uint32_t* BL = &kl4[nt >> 1][(nt & 1) << 1];
                mma16816(sA[nt], qfh[kk], BH);
                mma16816(sA[nt], qfh[kk], BL);
                mma16816(sA[nt], qfl[kk], BH);
            }
        }
        #pragma unroll
        for (int kk = 0; kk < 4; kk++) {
            uint32_t kb[4][4], kl4[4][4];
            #pragma unroll
            for (int q = 0; q < 4; q++) {
                uint32_t off = ((64 + q * 16) + brow) * AP + (kk * 16 + bkoff) * 2;
                ldsm4(kb[q],  sK + off);
                ldsm4(kl4[q], sK + AM2 + off);
            }
            #pragma unroll
            for (int nt = 0; nt < 8; nt++) {
                const uint32_t* BH = &kb[nt >> 1][(nt & 1) << 1];
                const uint32_t* BL = &kl4[nt >> 1][(nt & 1) << 1];
                mma16816(sB[nt], qfh[kk], BH);
                mma16816(sB[nt], qfh[kk], BL);
                mma16816(sB[nt], qfl[kk], BH);
            }
        }

        // ---- single online-softmax update over all 128 keys ----
        float mx0 = -INFINITY, mx1 = -INFINITY;
        #pragma unroll
        for (int nt = 0; nt < 8; nt++) {
            mx0 = fmaxf(mx0, fmaxf(fmaxf(sA[nt][0], sA[nt][1]), fmaxf(sB[nt][0], sB[nt][1])));
            mx1 = fmaxf(mx1, fmaxf(fmaxf(sA[nt][2], sA[nt][3]), fmaxf(sB[nt][2], sB[nt][3])));
        }
        mx0 = fmaxf(mx0, __shfl_xor_sync(0xffffffffu, mx0, 1));
        mx0 = fmaxf(mx0, __shfl_xor_sync(0xffffffffu, mx0, 2));
        mx1 = fmaxf(mx1, __shfl_xor_sync(0xffffffffu, mx1, 1));
        mx1 = fmaxf(mx1, __shfl_xor_sync(0xffffffffu, mx1, 2));
        float mn0 = fmaxf(m0_, mx0), mn1 = fmaxf(m1_, mx1);
        float corr0 = exp2f(m0_ - mn0), corr1 = exp2f(m1_ - mn1);
        m0_ = mn0; m1_ = mn1;

        float rs0 = 0.f, rs1 = 0.f;
        // exps + pack A
        uint32_t phA[4][4], plA[4][4];
        #pragma unroll
        for (int nt = 0; nt < 8; nt++) {
            sA[nt][0] = exp2f(sA[nt][0] - mn0); rs0 += sA[nt][0];
            sA[nt][1] = exp2f(sA[nt][1] - mn0); rs0 += sA[nt][1];
            sA[nt][2] = exp2f(sA[nt][2] - mn1); rs1 += sA[nt][2];
            sA[nt][3] = exp2f(sA[nt][3] - mn1); rs1 += sA[nt][3];
        }
        #pragma unroll
        for (int j = 0; j < 4; j++) {
            phA[j][0] = pack2(sA[2*j][0], sA[2*j][1]);
            phA[j][1] = pack2(sA[2*j][2], sA[2*j][3]);
            phA[j][2] = pack2(sA[2*j+1][0], sA[2*j+1][1]);
            phA[j][3] = pack2(sA[2*j+1][2], sA[2*j+1][3]);
            plA[j][0] = pack2_res(sA[2*j][0], sA[2*j][1], phA[j][0]);
            plA[j][1] = pack2_res(sA[2*j][2], sA[2*j][3], phA[j][1]);
            plA[j][2] = pack2_res(sA[2*j+1][0], sA[2*j+1][1], phA[j][2]);
            plA[j][3] = pack2_res(sA[2*j+1][2], sA[2*j+1][3], phA[j][3]);
        }

        // rescale o once
        #pragma unroll
        for (int dt = 0; dt < 8; dt++) {
            o[dt][0] *= corr0; o[dt][1] *= corr0;
            o[dt][2] *= corr1; o[dt][3] *= corr1;
        }

        // ---- PV(A) — interleaves with exps/pack of B below ----
        #pragma unroll
        for (int j = 0; j < 4; j++) {
            uint32_t vb[4][4], vl4[4][4];
            #pragma unroll
            for (int dq = 0; dq < 4; dq++) {
                uint32_t off = (j * 16 + arow) * AP + (dq * 16 + akoff) * 2;
                ldsm4t(vb[dq],  sV + off);
                ldsm4t(vl4[dq], sV + AM2 + off);
            }
            #pragma unroll
            for (int dt = 0; dt < 8; dt++) {
                const uint32_t* VH = &vb[dt >> 1][(dt & 1) << 1];
                const uint32_t* VL = &vl4[dt >> 1][(dt & 1) << 1];
                mma16816(o[dt], phA[j], VH);
                mma16816(o[dt], phA[j], VL);
                mma16816(o[dt], plA[j], VH);
            }
        }

        // exps + pack B (independent of PV(A) — ptxas interleaves)
        uint32_t phB[4][4], plB[4][4];
        #pragma unroll
        for (int nt = 0; nt < 8; nt++) {
            sB[nt][0] = exp2f(sB[nt][0] - mn0); rs0 += sB[nt][0];
            sB[nt][1] = exp2f(sB[nt][1] - mn0); rs0 += sB[nt][1];
            sB[nt][2] = exp2f(sB[nt][2] - mn1); rs1 += sB[nt][2];
            sB[nt][3] = exp2f(sB[nt][3] - mn1); rs1 += sB[nt][3];
        }
        #pragma unroll
        for (int j = 0; j < 4; j++) {
            phB[j][0] = pack2(sB[2*j][0], sB[2*j][1]);
            phB[j][1] = pack2(sB[2*j][2], sB[2*j][3]);
            phB[j][2] = pack2(sB[2*j+1][0], sB[2*j+1][1]);
            phB[j][3] = pack2(sB[2*j+1][2], sB[2*j+1][3]);
            plB[j][0] = pack2_res(sB[2*j][0], sB[2*j][1], phB[j][0]);
            plB[j][1] = pack2_res(sB[2*j][2], sB[2*j][3], phB[j][1]);
            plB[j][2] = pack2_res(sB[2*j+1][0], sB[2*j+1][1], phB[j][2]);
            plB[j][3] = pack2_res(sB[2*j+1][2], sB[2*j+1][3], phB[j][3]);
        }

        rs0 += __shfl_xor_sync(0xffffffffu, rs0, 1);
        rs0 += __shfl_xor_sync(0xffffffffu, rs0, 2);
        rs1 += __shfl_xor_sync(0xffffffffu, rs1, 1);
        rs1 += __shfl_xor_sync(0xffffffffu, rs1, 2);
        l0_ = l0_ * corr0 + rs0;
        l1_ = l1_ * corr1 + rs1;

        // ---- PV(B) ----
        #pragma unroll
        for (int j = 0; j < 4; j++) {
            uint32_t vb[4][4], vl4[4][4];
            #pragma unroll
            for (int dq = 0; dq < 4; dq++) {
                uint32_t off = ((64 + j * 16) + arow) * AP + (dq * 16 + akoff) * 2;
                ldsm4t(vb[dq],  sV + off);
                ldsm4t(vl4[dq], sV + AM2 + off);
            }
            #pragma unroll
            for (int dt = 0; dt < 8; dt++) {
                const uint32_t* VH = &vb[dt >> 1][(dt & 1) << 1];
                const uint32_t* VL = &vl4[dt >> 1][(dt & 1) << 1];
                mma16816(o[dt], phB[j], VH);
                mma16816(o[dt], phB[j], VL);
                mma16816(o[dt], plB[j], VH);
            }
        }
        __syncthreads();
    }

    const float inv0 = 1.f / l0_, inv1 = 1.f / l1_;
    const int gr = b * SEQ + q0 + wid * 16 + (lane >> 2);
    const int col = h * HEADDIM + ((lane & 3) << 1);
    #pragma unroll
    for (int dt = 0; dt < 8; dt++) {
        split_store(yh, yl, (size_t)gr * HID + col + dt * 8,
                    o[dt][0] * inv0, o[dt][1] * inv0);
        split_store(yh, yl, (size_t)(gr + 8) * HID + col + dt * 8,
                    o[dt][2] * inv1, o[dt][3] * inv1);
    }
}

// ---------------- converters ----------------
__global__ void convert_act(const float* __restrict__ in, bf16* __restrict__ h,
                            bf16* __restrict__ l, int n) {
    int i = (blockIdx.x * blockDim.x + threadIdx.x) << 2;
    if (i >= n) return;
    float4 v = *(const float4*)(in + i);
    uint32_t h0 = pack2(v.x, v.y), h1 = pack2(v.z, v.w);
    uint32_t l0 = pack2_res(v.x, v.y, h0), l1 = pack2_res(v.z, v.w, h1);
    *(uint32_t*)(h + i) = h0; *(uint32_t*)(h + i + 2) = h1;
    *(uint32_t*)(l + i) = l0; *(uint32_t*)(l + i + 2) = l1;
}

__global__ void trconv(const float* __restrict__ W, bf16* __restrict__ Th,
                       bf16* __restrict__ Tl, int K, int N) {
    __shared__ float t[32][33];
    const int n0 = blockIdx.x << 5, k0 = blockIdx.y << 5;
    const int tx = threadIdx.x, ty = threadIdx.y;
    #pragma unroll
    for (int j = 0; j < 32; j += 8)
        t[ty + j][tx] = W[(size_t)(k0 + ty + j) * N + n0 + tx];
    __syncthreads();
    #pragma unroll
    for (int j = 0; j < 32; j += 8) {
        float v = t[tx][ty + j];
        bf16 hv = __float2bfloat16(v);
        bf16 lv = __float2bfloat16(v - __bfloat162float(hv));
        size_t off = (size_t)(n0 + ty + j) * K + k0 + tx;
        Th[off] = hv;
        Tl[off] = lv;
    }
}

// ---------------- launch ----------------
extern "C" void kernel_launch(void* const* d_in, const int* in_sizes, int n_in,
                              void* d_out, int out_size) {
    const float* query     = (const float*)d_in[0];
    const float* key_value = (const float*)d_in[1];
    const float* Wq        = (const float*)d_in[2];
    const float* Wkv       = (const float*)d_in[3];
    const float* Wc        = (const float*)d_in[4];
    float* out = (float*)d_out;

    bf16 *qin_h, *qin_l, *kvin_h, *kvin_l, *qqh, *qql, *kvh, *kvl, *yh, *yl;
    bf16 *wqT_h, *wqT_l, *wkvT_h, *wkvT_l, *wcT_h, *wcT_l;
    cudaGetSymbolAddress((void**)&qin_h,  g_qin_h);
    cudaGetSymbolAddress((void**)&qin_l,  g_qin_l);
    cudaGetSymbolAddress((void**)&kvin_h, g_kvin_h);
    cudaGetSymbolAddress((void**)&kvin_l, g_kvin_l);
    cudaGetSymbolAddress((void**)&qqh,    g_qh);
    cudaGetSymbolAddress((void**)&qql,    g_ql);
    cudaGetSymbolAddress((void**)&kvh,    g_kvh);
    cudaGetSymbolAddress((void**)&kvl,    g_kvl);
    cudaGetSymbolAddress((void**)&yh,     g_yh);
    cudaGetSymbolAddress((void**)&yl,     g_yl);
    cudaGetSymbolAddress((void**)&wqT_h,  g_wqT_h);
    cudaGetSymbolAddress((void**)&wqT_l,  g_wqT_l);
    cudaGetSymbolAddress((void**)&wkvT_h, g_wkvT_h);
    cudaGetSymbolAddress((void**)&wkvT_l, g_wkvT_l);
    cudaGetSymbolAddress((void**)&wcT_h,  g_wcT_h);
    cudaGetSymbolAddress((void**)&wcT_l,  g_wcT_l);

    cudaFuncSetAttribute(proj_gemm, cudaFuncAttributeMaxDynamicSharedMemorySize, GSMEM);
    cudaFuncSetAttribute(out_gemm,  cudaFuncAttributeMaxDynamicSharedMemorySize, GSMEM);
    cudaFuncSetAttribute(attn_mma,  cudaFuncAttributeMaxDynamicSharedMemorySize, ASMEM);

    {
        int n = MROWS * HID;
        convert_act<<<n / 4 / 256, 256>>>(query, qin_h, qin_l, n);
        convert_act<<<n / 4 / 256, 256>>>(key_value, kvin_h, kvin_l, n);
    }
    trconv<<<dim3(HID / 32, HID / 32),     dim3(32, 8)>>>(Wq,  wqT_h,  wqT_l,  HID, HID);
    trconv<<<dim3(2 * HID / 32, HID / 32), dim3(32, 8)>>>(Wkv, wkvT_h, wkvT_l, HID, 2 * HID);
    trconv<<<dim3(HID / 32, HID / 32),     dim3(32, 8)>>>(Wc,  wcT_h,  wcT_l,  HID, HID);

    // merged projections: bx<8 -> q-proj (scale folds 0.125*log2e), else kv-proj
    proj_gemm<<<dim3(HID / 128 + 2 * HID / 128, MROWS / 128), 256, GSMEM>>>(
        qin_h, qin_l, kvin_h, kvin_l,
        wqT_h, wqT_l, wkvT_h, wkvT_l,
        qqh, qql, kvh, kvl);

    attn_mma<<<dim3(SEQ / 128, BATCH * NHEADS), 256, ASMEM>>>(qqh, qql, kvh, kvl, yh, yl);

    out_gemm<<<dim3(HID / 128, MROWS / 128), 256, GSMEM>>>(yh, yl, wcT_h, wcT_l, out);
}